// round 13
// baseline (speedup 1.0000x reference)
#include <cuda_runtime.h>
#include <cuda_fp16.h>
#include <stdint.h>
#include <math.h>

#define B_    128
#define N_    196
#define ENC_  2048
#define DEC_  512
#define ATT_  512
#define M_    (B_ * N_)          // 25088 rows
#define KF_TOT (ENC_ / 16)       // 128 k16 fragments
#define FN_TOT (ATT_ / 8)        // 64  n8 fragments

// gemm tiling: block 128m x 128n x 64k, 2-stage, 2 CTAs/SM  (R8 dataflow, FROZEN)
#define NKS        32            // k-steps of 64
#define STAGE_U32  12288         // 48KB per stage
#define SMEM_BYTES (2 * STAGE_U32 * 4)   // 98304

#define ATT2_BLOCKS 32           // 16 a-chunks x 2 b-halves

// ---- scratch (__device__ globals: sanctioned no-alloc workaround) ----
__device__ float    g_att2[B_ * ATT_];
__device__ float    g_epart[M_ * 4];
__device__ uint32_t g_Bf[FN_TOT * KF_TOT * 64];   // B fp16 frag-major, permuted k

// ============================================================
// helpers
// ============================================================
__device__ __forceinline__ uint32_t pack_h2(__half lo, __half hi) {
    __half2 p; p.x = lo; p.y = hi;       // .x = low 16 bits (lower k index)
    return *reinterpret_cast<uint32_t*>(&p);
}
__device__ __forceinline__ uint32_t cvt2h(float hi, float lo) {
    uint32_t r;
    asm("cvt.rn.f16x2.f32 %0, %1, %2;" : "=r"(r) : "f"(hi), "f"(lo));
    return r;
}
__device__ __forceinline__ void cp16(uint32_t saddr, const void* g) {
    asm volatile("cp.async.cg.shared.global [%0], [%1], 16;\n" :: "r"(saddr), "l"(g));
}
__device__ __forceinline__ void cp_commit() { asm volatile("cp.async.commit_group;\n"); }
template <int NN> __device__ __forceinline__ void cp_wait() {
    asm volatile("cp.async.wait_group %0;\n" :: "n"(NN));
}
__device__ __forceinline__ void mma16816(float c[4], const uint32_t a[4], const uint32_t b[2]) {
    asm volatile(
        "mma.sync.aligned.m16n8k16.row.col.f32.f16.f16.f32 "
        "{%0,%1,%2,%3}, {%4,%5,%6,%7}, {%8,%9}, {%0,%1,%2,%3};\n"
        : "+f"(c[0]), "+f"(c[1]), "+f"(c[2]), "+f"(c[3])
        : "r"(a[0]), "r"(a[1]), "r"(a[2]), "r"(a[3]),
          "r"(b[0]), "r"(b[1]));
}

// ============================================================
// Kernel 1 (fused prep):
//   blocks 0..31   -> att2 (tiled: 32a x 64b per block, dec in smem)
//   blocks 32..1055 -> prepackB (fp16 frag-major, permuted k)
// ============================================================
__global__ __launch_bounds__(512)
void prep_kernel(const float* __restrict__ dec,
                 const float* __restrict__ Wdec,
                 const float* __restrict__ bdec,
                 const float* __restrict__ Wenc) {
    __shared__ float ds[64][128];    // 32KB d-tile of dec
    const int tid = threadIdx.x;
    if (blockIdx.x < ATT2_BLOCKS) {
        // ---- att2: block = (ax: 32 a's) x (bh: 64 b's) ----
        const int ax = blockIdx.x >> 1, bh = blockIdx.x & 1;
        const int a  = ax * 32 + (tid & 31);
        const int bg = tid >> 5;               // 0..15 -> 4 b's each
        const int b0 = bh * 64 + bg * 4;

        float acc0 = 0.f, acc1 = 0.f, acc2 = 0.f, acc3 = 0.f;
#pragma unroll
        for (int dt = 0; dt < DEC_; dt += 128) {
            __syncthreads();                   // protect previous tile
#pragma unroll
            for (int j = 0; j < 4; j++) {
                int lin = j * 512 + tid;       // 0..2047
                int row = lin >> 5;            // 0..63 (b within half)
                int c4  = lin & 31;            // float4 col
                *reinterpret_cast<float4*>(&ds[row][c4 * 4]) =
                    *reinterpret_cast<const float4*>(
                        &dec[(size_t)(bh * 64 + row) * DEC_ + dt + c4 * 4]);
            }
            __syncthreads();
#pragma unroll 8
            for (int d = 0; d < 128; d++) {
                float w = Wdec[(size_t)(dt + d) * ATT_ + a];
                acc0 += ds[bg * 4 + 0][d] * w;
                acc1 += ds[bg * 4 + 1][d] * w;
                acc2 += ds[bg * 4 + 2][d] * w;
                acc3 += ds[bg * 4 + 3][d] * w;
            }
        }
        float bd = bdec[a];
        g_att2[(size_t)(b0 + 0) * ATT_ + a] = acc0 + bd;
        g_att2[(size_t)(b0 + 1) * ATT_ + a] = acc1 + bd;
        g_att2[(size_t)(b0 + 2) * ATT_ + a] = acc2 + bd;
        g_att2[(size_t)(b0 + 3) * ATT_ + a] = acc3 + bd;
    } else {
        // ---- prepackB: W_enc [K][N] -> fp16 frag-major, permuted k ----
        int idx = (blockIdx.x - ATT2_BLOCKS) * 512 + tid;   // < 524288
        int reg  = idx & 1;                  // kreg
        int lane = (idx >> 1) & 31;
        int kf   = (idx >> 6) & (KF_TOT - 1);
        int fn   = idx >> 13;
        int n = fn * 8 + (lane >> 2);
        int k = kf * 16 + (lane & 3) * 4 + reg * 2;   // permuted
        float v0 = Wenc[(size_t)k * ATT_ + n];
        float v1 = Wenc[(size_t)(k + 1) * ATT_ + n];
        g_Bf[idx] = pack_h2(__float2half_rn(v0), __float2half_rn(v1));
    }
}

// ============================================================
// Kernel 2: HMMA GEMM (1-term fp16, A converted in-kernel) + epilogue
//   == exact R8/R11 dataflow (measured ~160us) — FROZEN ==
// ============================================================
__global__ __launch_bounds__(256, 2)
void gemm_e_kernel(const float* __restrict__ enc,
                   const float* __restrict__ benc,
                   const float* __restrict__ Wfull) {
    extern __shared__ uint32_t sm[];   // 2 stages x 12288 u32
    const int tid = threadIdx.x;
    const int lane = tid & 31, wid = tid >> 5;
    const int warpM = wid & 3, warpN = wid >> 2;   // 4M x 2N
    const int nchunk = blockIdx.x;     // 0..3
    const int mtile  = blockIdx.y;     // 0..195
    const int m0g = mtile * 128;
    const int g = lane >> 2, tig = lane & 3;

    const uint32_t smbase = (uint32_t)__cvta_generic_to_shared(sm);

    float acc[2][8][4];
#pragma unroll
    for (int i = 0; i < 2; i++)
#pragma unroll
        for (int j = 0; j < 8; j++)
#pragma unroll
            for (int q = 0; q < 4; q++) acc[i][j][q] = 0.f;

    // ---- async load of k-step ks (64 k): A raw fp32 + B fp16; 12/thread ----
    auto issue = [&](int ks, int st) {
        const uint32_t so = smbase + (uint32_t)(st * STAGE_U32) * 4u;
#pragma unroll
        for (int i = 0; i < 12; i++) {
            int c = i * 256 + tid;           // 0..3071
            uint32_t dst;
            const void* src;
            if (c < 2048) {                  // A: row(128) x chunk16(16B=4 fp32)
                int row = c >> 4, cc = c & 15;
                int csw = (cc + row * 4) & 15;
                src = enc + (size_t)(m0g + row) * ENC_ + ks * 64 + cc * 4;
                dst = so + (uint32_t)(row * 64 + csw * 4) * 4u;
            } else {                         // B: fn16 kf4 q16
                int d = c - 2048;
                int fn = d >> 6, kf = (d >> 4) & 3, q = d & 15;
                src = g_Bf + ((size_t)(nchunk * 16 + fn) * KF_TOT + (ks * 4 + kf)) * 64 + q * 4;
                dst = so + (uint32_t)(8192 + (fn * 4 + kf) * 64 + q * 4) * 4u;
            }
            cp16(dst, src);
        }
        cp_commit();
    };

    issue(0, 0);

    for (int s = 0; s < NKS; s++) {
        const int st = s & 1;
        cp_wait<0>();                 // only group s outstanding here
        __syncthreads();              // all warps done reading buffer s-1
        if (s + 1 < NKS) issue(s + 1, st ^ 1);

        const int sb = st * STAGE_U32;
#pragma unroll
        for (int kf = 0; kf < 4; kf++) {
            // A fragments: 2x LDS.128 fp32 + 4 cvt per fm
            uint32_t a[2][4];
#pragma unroll
            for (int fm = 0; fm < 2; fm++) {
                int rbase = (warpM * 2 + fm) * 16;
                int r0 = rbase + g, r1 = rbase + 8 + g;
                int c0 = ((kf * 4 + tig) + r0 * 4) & 15;
                int c1 = ((kf * 4 + tig) + r1 * 4) & 15;
                float4 f0 = *reinterpret_cast<const float4*>(&sm[sb + r0 * 64 + c0 * 4]);
                float4 f1 = *reinterpret_cast<const float4*>(&sm[sb + r1 * 64 + c1 * 4]);
                a[fm][0] = cvt2h(f0.y, f0.x);
                a[fm][1] = cvt2h(f1.y, f1.x);
                a[fm][2] = cvt2h(f0.w, f0.z);
                a[fm][3] = cvt2h(f1.w, f1.z);
            }
            // B fragments: one LDS.64 per fn
            uint32_t b[8][2];
#pragma unroll
            for (int fn = 0; fn < 8; fn++) {
                int fnAbs = warpN * 8 + fn;
                uint2 v = *reinterpret_cast<const uint2*>(
                    &sm[sb + 8192 + (fnAbs * 4 + kf) * 64 + lane * 2]);
                b[fn][0] = v.x; b[fn][1] = v.y;
            }
#pragma unroll
            for (int fm = 0; fm < 2; fm++)
#pragma unroll
                for (int fn = 0; fn < 8; fn++)
                    mma16816(acc[fm][fn], a[fm], b[fn]);
        }
    }

    // ---- fused epilogue: v = relu(acc + b_enc + att2); e += v * W_full ----
    float ep[2][2] = {{0.f, 0.f}, {0.f, 0.f}};
#pragma unroll
    for (int fm = 0; fm < 2; fm++) {
        int r0 = warpM * 32 + fm * 16 + g;
        int b0 = (m0g + r0) / N_;
        int b1 = (m0g + r0 + 8) / N_;
#pragma unroll
        for (int fn = 0; fn < 8; fn++) {
            int a0i = nchunk * 128 + warpN * 64 + fn * 8 + tig * 2;
            int a1i = a0i + 1;
            float w0 = Wfull[a0i], w1 = Wfull[a1i];
            float be0 = benc[a0i], be1 = benc[a1i];
            float t00 = g_att2[b0 * ATT_ + a0i];
            float t01 = g_att2[b0 * ATT_ + a1i];
            float t10 = g_att2[b1 * ATT_ + a0i];
            float t11 = g_att2[b1 * ATT_ + a1i];
            ep[fm][0] += fmaxf(acc[fm][fn][0] + be0 + t00, 0.f) * w0;
            ep[fm][0] += fmaxf(acc[fm][fn][1] + be1 + t01, 0.f) * w1;
            ep[fm][1] += fmaxf(acc[fm][fn][2] + be0 + t10, 0.f) * w0;
            ep[fm][1] += fmaxf(acc[fm][fn][3] + be1 + t11, 0.f) * w1;
        }
    }
#pragma unroll
    for (int off = 1; off <= 2; off <<= 1)
#pragma unroll
        for (int fm = 0; fm < 2; fm++) {
            ep[fm][0] += __shfl_xor_sync(0xffffffffu, ep[fm][0], off);
            ep[fm][1] += __shfl_xor_sync(0xffffffffu, ep[fm][1], off);
        }

    __syncthreads();
    float* e_red = reinterpret_cast<float*>(sm);  // [128][2]
    if (tig == 0) {
#pragma unroll
        for (int fm = 0; fm < 2; fm++) {
            int r0 = warpM * 32 + fm * 16 + g;
            e_red[r0 * 2 + warpN]       = ep[fm][0];
            e_red[(r0 + 8) * 2 + warpN] = ep[fm][1];
        }
    }
    __syncthreads();
    if (tid < 128)
        g_epart[(size_t)(m0g + tid) * 4 + nchunk] = e_red[tid * 2] + e_red[tid * 2 + 1];
}

// ============================================================
// Kernel 3: fused softmax + awe (DRAM-transfer-bound; unchanged)
// ============================================================
__global__ void awe_kernel(const float* __restrict__ enc,
                           const float* __restrict__ bfull_p,
                           float* __restrict__ out_alpha,
                           float* __restrict__ out_awe) {
    __shared__ float al[N_];
    __shared__ float red[256];
    int b = blockIdx.y, tid = threadIdx.x;
    float bfull = *bfull_p;

    // ---- softmax over n (196) ----
    float ev = -INFINITY;
    float sval = 0.f;
    if (tid < N_) {
        const float* p = &g_epart[(size_t)(b * N_ + tid) * 4];
        sval = bfull + p[0] + p[1] + p[2] + p[3];
        ev = sval;
    }
    red[tid] = ev; __syncthreads();
#pragma unroll
    for (int off = 128; off > 0; off >>= 1) {
        if (tid < off) red[tid] = fmaxf(red[tid], red[tid + off]);
        __syncthreads();
    }
    float mx = red[0]; __syncthreads();
    float ex = 0.f;
    if (tid < N_) ex = expf(sval - mx);
    red[tid] = ex; __syncthreads();
#pragma unroll
    for (int off = 128; off > 0; off >>= 1) {
        if (tid < off) red[tid] += red[tid + off];
        __syncthreads();
    }
    float inv = 1.f / red[0];
    if (tid < N_) {
        float a = ex * inv;
        al[tid] = a;
        if (blockIdx.x == 0) out_alpha[b * N_ + tid] = a;
    }
    __syncthreads();

    // ---- weighted encoding: 7 chains (196 = 7*28) ----
    int e0 = (blockIdx.x * 256 + tid) * 4;
    const float4* p = reinterpret_cast<const float4*>(enc + (size_t)b * N_ * ENC_ + e0);
    float4 acc[7];
#pragma unroll
    for (int c = 0; c < 7; c++) acc[c] = make_float4(0.f, 0.f, 0.f, 0.f);

#pragma unroll 2
    for (int n = 0; n < 28; n++) {
        float4 v[7];
#pragma unroll
        for (int c = 0; c < 7; c++)
            v[c] = p[(size_t)(n + c * 28) * (ENC_ / 4)];
#pragma unroll
        for (int c = 0; c < 7; c++) {
            float w = al[n + c * 28];
            acc[c].x += w * v[c].x; acc[c].y += w * v[c].y;
            acc[c].z += w * v[c].z; acc[c].w += w * v[c].w;
        }
    }
    float4 r;
    r.x = ((acc[0].x + acc[1].x) + (acc[2].x + acc[3].x)) + ((acc[4].x + acc[5].x) + acc[6].x);
    r.y = ((acc[0].y + acc[1].y) + (acc[2].y + acc[3].y)) + ((acc[4].y + acc[5].y) + acc[6].y);
    r.z = ((acc[0].z + acc[1].z) + (acc[2].z + acc[3].z)) + ((acc[4].z + acc[5].z) + acc[6].z);
    r.w = ((acc[0].w + acc[1].w) + (acc[2].w + acc[3].w)) + ((acc[4].w + acc[5].w) + acc[6].w);
    *reinterpret_cast<float4*>(out_awe + (size_t)b * ENC_ + e0) = r;
}

// ============================================================
extern "C" void kernel_launch(void* const* d_in, const int* in_sizes, int n_in,
                              void* d_out, int out_size) {
    const float* enc   = (const float*)d_in[0];
    const float* dech  = (const float*)d_in[1];
    const float* Wenc  = (const float*)d_in[2];
    const float* benc  = (const float*)d_in[3];
    const float* Wdec  = (const float*)d_in[4];
    const float* bdec  = (const float*)d_in[5];
    const float* Wfull = (const float*)d_in[6];
    const float* bfull = (const float*)d_in[7];

    float* out       = (float*)d_out;
    float* out_awe   = out;
    float* out_alpha = out + (size_t)B_ * ENC_;

    cudaFuncSetAttribute(gemm_e_kernel,
                         cudaFuncAttributeMaxDynamicSharedMemorySize, SMEM_BYTES);

    // fused att2 (32 tiled blocks) + prepackB (1024 blocks)
    prep_kernel<<<ATT2_BLOCKS + 1024, 512>>>(dech, Wdec, bdec, Wenc);

    dim3 g2(4, 196);                           // nchunk fastest -> A L2 reuse
    gemm_e_kernel<<<g2, 256, SMEM_BYTES>>>(enc, benc, Wfull);

    dim3 g3(2, B_);
    awe_kernel<<<g3, 256>>>(enc, bfull, out_alpha, out_awe);
}

// round 14
// speedup vs baseline: 1.2434x; 1.2434x over previous
#include <cuda_runtime.h>
#include <cuda_fp16.h>
#include <stdint.h>
#include <math.h>

#define B_    128
#define N_    196
#define ENC_  2048
#define DEC_  512
#define ATT_  512
#define M_    (B_ * N_)          // 25088 rows
#define KF_TOT (ENC_ / 16)       // 128 k16 fragments
#define FN_TOT (ATT_ / 8)        // 64  n8 fragments

// gemm tiling: block 128m x 128n x 64k, 2-stage, 2 CTAs/SM  (R8 dataflow, FROZEN)
#define NKS        32            // k-steps of 64
#define STAGE_U32  12288         // 48KB per stage
#define SMEM_BYTES (2 * STAGE_U32 * 4)   // 98304

// ---- scratch (__device__ globals: sanctioned no-alloc workaround) ----
__device__ float    g_att2[B_ * ATT_];
__device__ float    g_epart[M_ * 4];
__device__ uint32_t g_Bf[FN_TOT * KF_TOT * 64];   // B fp16 frag-major, permuted k

// ============================================================
// helpers
// ============================================================
__device__ __forceinline__ uint32_t pack_h2(__half lo, __half hi) {
    __half2 p; p.x = lo; p.y = hi;       // .x = low 16 bits (lower k index)
    return *reinterpret_cast<uint32_t*>(&p);
}
__device__ __forceinline__ uint32_t cvt2h(float hi, float lo) {
    uint32_t r;
    asm("cvt.rn.f16x2.f32 %0, %1, %2;" : "=r"(r) : "f"(hi), "f"(lo));
    return r;
}
__device__ __forceinline__ void cp16(uint32_t saddr, const void* g) {
    asm volatile("cp.async.cg.shared.global [%0], [%1], 16;\n" :: "r"(saddr), "l"(g));
}
__device__ __forceinline__ void cp_commit() { asm volatile("cp.async.commit_group;\n"); }
template <int NN> __device__ __forceinline__ void cp_wait() {
    asm volatile("cp.async.wait_group %0;\n" :: "n"(NN));
}
__device__ __forceinline__ void mma16816(float c[4], const uint32_t a[4], const uint32_t b[2]) {
    asm volatile(
        "mma.sync.aligned.m16n8k16.row.col.f32.f16.f16.f32 "
        "{%0,%1,%2,%3}, {%4,%5,%6,%7}, {%8,%9}, {%0,%1,%2,%3};\n"
        : "+f"(c[0]), "+f"(c[1]), "+f"(c[2]), "+f"(c[3])
        : "r"(a[0]), "r"(a[1]), "r"(a[2]), "r"(a[3]),
          "r"(b[0]), "r"(b[1]));
}

// ============================================================
// Kernel 1: att2 = decoder_hidden @ W_dec + b_dec   (fp32 exact)
//   grid 128 = (16 a-chunks) x (8 b-groups); block 512 = 32a x 16b
//   16 b's share each Wdec read -> Wdec traffic 8MB (16x less than naive)
// ============================================================
__global__ __launch_bounds__(512)
void att2_kernel(const float* __restrict__ dec,
                 const float* __restrict__ Wdec,
                 const float* __restrict__ bdec) {
    __shared__ float ds[16][DEC_];    // 32KB: 16 dec rows
    const int tid = threadIdx.x;
    const int ax  = blockIdx.x & 15;
    const int bgp = blockIdx.x >> 4;
    const int a  = ax * 32 + (tid & 31);
    const int bl = tid >> 5;          // 0..15
    const int b  = bgp * 16 + bl;

    // stage 16 dec rows (16*512 floats = 2048 float4, 4 per thread)
#pragma unroll
    for (int j = 0; j < 4; j++) {
        int lin = j * 512 + tid;
        int row = lin >> 7;           // 0..15
        int c4  = lin & 127;
        *reinterpret_cast<float4*>(&ds[row][c4 * 4]) =
            *reinterpret_cast<const float4*>(&dec[(size_t)(bgp * 16 + row) * DEC_ + c4 * 4]);
    }
    __syncthreads();

    // 4 accumulator chains over d
    float a0 = 0.f, a1 = 0.f, a2 = 0.f, a3 = 0.f;
#pragma unroll 4
    for (int d = 0; d < DEC_; d += 4) {
        float w0 = Wdec[(size_t)(d + 0) * ATT_ + a];
        float w1 = Wdec[(size_t)(d + 1) * ATT_ + a];
        float w2 = Wdec[(size_t)(d + 2) * ATT_ + a];
        float w3 = Wdec[(size_t)(d + 3) * ATT_ + a];
        a0 += ds[bl][d + 0] * w0;
        a1 += ds[bl][d + 1] * w1;
        a2 += ds[bl][d + 2] * w2;
        a3 += ds[bl][d + 3] * w3;
    }
    g_att2[(size_t)b * ATT_ + a] = ((a0 + a1) + (a2 + a3)) + bdec[a];
}

// ============================================================
// Prepack B: W_enc [K][N] -> fp16 frag-major with PERMUTED k layout
//   position (tig, kreg, elem) holds actual k = kf*16 + tig*4 + kreg*2 + elem
// ============================================================
__global__ void prepackB(const float* __restrict__ Wenc) {
    int idx = blockIdx.x * 256 + threadIdx.x;
    int reg  = idx & 1;                  // kreg
    int lane = (idx >> 1) & 31;
    int kf   = (idx >> 6) & (KF_TOT - 1);
    int fn   = idx >> 13;
    int n = fn * 8 + (lane >> 2);
    int k = kf * 16 + (lane & 3) * 4 + reg * 2;   // permuted
    float v0 = Wenc[(size_t)k * ATT_ + n];
    float v1 = Wenc[(size_t)(k + 1) * ATT_ + n];
    g_Bf[idx] = pack_h2(__float2half_rn(v0), __float2half_rn(v1));
}

// ============================================================
// Kernel 2: HMMA GEMM (1-term fp16, A converted in-kernel) + epilogue
//   == exact R8/R11 dataflow (measured ~160us) — FROZEN ==
// ============================================================
__global__ __launch_bounds__(256, 2)
void gemm_e_kernel(const float* __restrict__ enc,
                   const float* __restrict__ benc,
                   const float* __restrict__ Wfull) {
    extern __shared__ uint32_t sm[];   // 2 stages x 12288 u32
    const int tid = threadIdx.x;
    const int lane = tid & 31, wid = tid >> 5;
    const int warpM = wid & 3, warpN = wid >> 2;   // 4M x 2N
    const int nchunk = blockIdx.x;     // 0..3
    const int mtile  = blockIdx.y;     // 0..195
    const int m0g = mtile * 128;
    const int g = lane >> 2, tig = lane & 3;

    const uint32_t smbase = (uint32_t)__cvta_generic_to_shared(sm);

    float acc[2][8][4];
#pragma unroll
    for (int i = 0; i < 2; i++)
#pragma unroll
        for (int j = 0; j < 8; j++)
#pragma unroll
            for (int q = 0; q < 4; q++) acc[i][j][q] = 0.f;

    // ---- async load of k-step ks (64 k): A raw fp32 + B fp16; 12/thread ----
    auto issue = [&](int ks, int st) {
        const uint32_t so = smbase + (uint32_t)(st * STAGE_U32) * 4u;
#pragma unroll
        for (int i = 0; i < 12; i++) {
            int c = i * 256 + tid;           // 0..3071
            uint32_t dst;
            const void* src;
            if (c < 2048) {                  // A: row(128) x chunk16(16B=4 fp32)
                int row = c >> 4, cc = c & 15;
                int csw = (cc + row * 4) & 15;
                src = enc + (size_t)(m0g + row) * ENC_ + ks * 64 + cc * 4;
                dst = so + (uint32_t)(row * 64 + csw * 4) * 4u;
            } else {                         // B: fn16 kf4 q16
                int d = c - 2048;
                int fn = d >> 6, kf = (d >> 4) & 3, q = d & 15;
                src = g_Bf + ((size_t)(nchunk * 16 + fn) * KF_TOT + (ks * 4 + kf)) * 64 + q * 4;
                dst = so + (uint32_t)(8192 + (fn * 4 + kf) * 64 + q * 4) * 4u;
            }
            cp16(dst, src);
        }
        cp_commit();
    };

    issue(0, 0);

    for (int s = 0; s < NKS; s++) {
        const int st = s & 1;
        cp_wait<0>();                 // only group s outstanding here
        __syncthreads();              // all warps done reading buffer s-1
        if (s + 1 < NKS) issue(s + 1, st ^ 1);

        const int sb = st * STAGE_U32;
#pragma unroll
        for (int kf = 0; kf < 4; kf++) {
            // A fragments: 2x LDS.128 fp32 + 4 cvt per fm
            uint32_t a[2][4];
#pragma unroll
            for (int fm = 0; fm < 2; fm++) {
                int rbase = (warpM * 2 + fm) * 16;
                int r0 = rbase + g, r1 = rbase + 8 + g;
                int c0 = ((kf * 4 + tig) + r0 * 4) & 15;
                int c1 = ((kf * 4 + tig) + r1 * 4) & 15;
                float4 f0 = *reinterpret_cast<const float4*>(&sm[sb + r0 * 64 + c0 * 4]);
                float4 f1 = *reinterpret_cast<const float4*>(&sm[sb + r1 * 64 + c1 * 4]);
                a[fm][0] = cvt2h(f0.y, f0.x);
                a[fm][1] = cvt2h(f1.y, f1.x);
                a[fm][2] = cvt2h(f0.w, f0.z);
                a[fm][3] = cvt2h(f1.w, f1.z);
            }
            // B fragments: one LDS.64 per fn
            uint32_t b[8][2];
#pragma unroll
            for (int fn = 0; fn < 8; fn++) {
                int fnAbs = warpN * 8 + fn;
                uint2 v = *reinterpret_cast<const uint2*>(
                    &sm[sb + 8192 + (fnAbs * 4 + kf) * 64 + lane * 2]);
                b[fn][0] = v.x; b[fn][1] = v.y;
            }
#pragma unroll
            for (int fm = 0; fm < 2; fm++)
#pragma unroll
                for (int fn = 0; fn < 8; fn++)
                    mma16816(acc[fm][fn], a[fm], b[fn]);
        }
    }

    // ---- fused epilogue: v = relu(acc + b_enc + att2); e += v * W_full ----
    float ep[2][2] = {{0.f, 0.f}, {0.f, 0.f}};
#pragma unroll
    for (int fm = 0; fm < 2; fm++) {
        int r0 = warpM * 32 + fm * 16 + g;
        int b0 = (m0g + r0) / N_;
        int b1 = (m0g + r0 + 8) / N_;
#pragma unroll
        for (int fn = 0; fn < 8; fn++) {
            int a0i = nchunk * 128 + warpN * 64 + fn * 8 + tig * 2;
            int a1i = a0i + 1;
            float w0 = Wfull[a0i], w1 = Wfull[a1i];
            float be0 = benc[a0i], be1 = benc[a1i];
            float t00 = g_att2[b0 * ATT_ + a0i];
            float t01 = g_att2[b0 * ATT_ + a1i];
            float t10 = g_att2[b1 * ATT_ + a0i];
            float t11 = g_att2[b1 * ATT_ + a1i];
            ep[fm][0] += fmaxf(acc[fm][fn][0] + be0 + t00, 0.f) * w0;
            ep[fm][0] += fmaxf(acc[fm][fn][1] + be1 + t01, 0.f) * w1;
            ep[fm][1] += fmaxf(acc[fm][fn][2] + be0 + t10, 0.f) * w0;
            ep[fm][1] += fmaxf(acc[fm][fn][3] + be1 + t11, 0.f) * w1;
        }
    }
#pragma unroll
    for (int off = 1; off <= 2; off <<= 1)
#pragma unroll
        for (int fm = 0; fm < 2; fm++) {
            ep[fm][0] += __shfl_xor_sync(0xffffffffu, ep[fm][0], off);
            ep[fm][1] += __shfl_xor_sync(0xffffffffu, ep[fm][1], off);
        }

    __syncthreads();
    float* e_red = reinterpret_cast<float*>(sm);  // [128][2]
    if (tig == 0) {
#pragma unroll
        for (int fm = 0; fm < 2; fm++) {
            int r0 = warpM * 32 + fm * 16 + g;
            e_red[r0 * 2 + warpN]       = ep[fm][0];
            e_red[(r0 + 8) * 2 + warpN] = ep[fm][1];
        }
    }
    __syncthreads();
    if (tid < 128)
        g_epart[(size_t)(m0g + tid) * 4 + nchunk] = e_red[tid * 2] + e_red[tid * 2 + 1];
}

// ============================================================
// Kernel 3: fused softmax + awe (DRAM-transfer-bound; R11 form)
// ============================================================
__global__ void awe_kernel(const float* __restrict__ enc,
                           const float* __restrict__ bfull_p,
                           float* __restrict__ out_alpha,
                           float* __restrict__ out_awe) {
    __shared__ float al[N_];
    __shared__ float red[256];
    int b = blockIdx.y, tid = threadIdx.x;
    float bfull = *bfull_p;

    // ---- softmax over n (196) ----
    float ev = -INFINITY;
    float sval = 0.f;
    if (tid < N_) {
        const float* p = &g_epart[(size_t)(b * N_ + tid) * 4];
        sval = bfull + p[0] + p[1] + p[2] + p[3];
        ev = sval;
    }
    red[tid] = ev; __syncthreads();
#pragma unroll
    for (int off = 128; off > 0; off >>= 1) {
        if (tid < off) red[tid] = fmaxf(red[tid], red[tid + off]);
        __syncthreads();
    }
    float mx = red[0]; __syncthreads();
    float ex = 0.f;
    if (tid < N_) ex = expf(sval - mx);
    red[tid] = ex; __syncthreads();
#pragma unroll
    for (int off = 128; off > 0; off >>= 1) {
        if (tid < off) red[tid] += red[tid + off];
        __syncthreads();
    }
    float inv = 1.f / red[0];
    if (tid < N_) {
        float a = ex * inv;
        al[tid] = a;
        if (blockIdx.x == 0) out_alpha[b * N_ + tid] = a;
    }
    __syncthreads();

    // ---- weighted encoding: float4, 7 accumulator chains (28*7=196) ----
    int e0 = (blockIdx.x * 256 + tid) * 4;
    const float4* p = reinterpret_cast<const float4*>(enc + (size_t)b * N_ * ENC_ + e0);
    float4 a0 = make_float4(0.f, 0.f, 0.f, 0.f);
    float4 a1 = make_float4(0.f, 0.f, 0.f, 0.f);
    float4 a2 = make_float4(0.f, 0.f, 0.f, 0.f);
    float4 a3 = make_float4(0.f, 0.f, 0.f, 0.f);
    float4 a4 = make_float4(0.f, 0.f, 0.f, 0.f);
    float4 a5 = make_float4(0.f, 0.f, 0.f, 0.f);
    float4 a6 = make_float4(0.f, 0.f, 0.f, 0.f);
#pragma unroll 4
    for (int n = 0; n < 28; n++) {
        float4 v0 = p[(size_t)n * (ENC_ / 4)];
        float4 v1 = p[(size_t)(n + 28) * (ENC_ / 4)];
        float4 v2 = p[(size_t)(n + 56) * (ENC_ / 4)];
        float4 v3 = p[(size_t)(n + 84) * (ENC_ / 4)];
        float4 v4 = p[(size_t)(n + 112) * (ENC_ / 4)];
        float4 v5 = p[(size_t)(n + 140) * (ENC_ / 4)];
        float4 v6 = p[(size_t)(n + 168) * (ENC_ / 4)];
        float w0 = al[n], w1 = al[n + 28], w2 = al[n + 56], w3 = al[n + 84];
        float w4 = al[n + 112], w5 = al[n + 140], w6 = al[n + 168];
        a0.x += w0 * v0.x; a0.y += w0 * v0.y; a0.z += w0 * v0.z; a0.w += w0 * v0.w;
        a1.x += w1 * v1.x; a1.y += w1 * v1.y; a1.z += w1 * v1.z; a1.w += w1 * v1.w;
        a2.x += w2 * v2.x; a2.y += w2 * v2.y; a2.z += w2 * v2.z; a2.w += w2 * v2.w;
        a3.x += w3 * v3.x; a3.y += w3 * v3.y; a3.z += w3 * v3.z; a3.w += w3 * v3.w;
        a4.x += w4 * v4.x; a4.y += w4 * v4.y; a4.z += w4 * v4.z; a4.w += w4 * v4.w;
        a5.x += w5 * v5.x; a5.y += w5 * v5.y; a5.z += w5 * v5.z; a5.w += w5 * v5.w;
        a6.x += w6 * v6.x; a6.y += w6 * v6.y; a6.z += w6 * v6.z; a6.w += w6 * v6.w;
    }
    float4 r;
    r.x = ((a0.x + a1.x) + (a2.x + a3.x)) + ((a4.x + a5.x) + a6.x);
    r.y = ((a0.y + a1.y) + (a2.y + a3.y)) + ((a4.y + a5.y) + a6.y);
    r.z = ((a0.z + a1.z) + (a2.z + a3.z)) + ((a4.z + a5.z) + a6.z);
    r.w = ((a0.w + a1.w) + (a2.w + a3.w)) + ((a4.w + a5.w) + a6.w);
    *reinterpret_cast<float4*>(out_awe + (size_t)b * ENC_ + e0) = r;
}

// ============================================================
extern "C" void kernel_launch(void* const* d_in, const int* in_sizes, int n_in,
                              void* d_out, int out_size) {
    const float* enc   = (const float*)d_in[0];
    const float* dech  = (const float*)d_in[1];
    const float* Wenc  = (const float*)d_in[2];
    const float* benc  = (const float*)d_in[3];
    const float* Wdec  = (const float*)d_in[4];
    const float* bdec  = (const float*)d_in[5];
    const float* Wfull = (const float*)d_in[6];
    const float* bfull = (const float*)d_in[7];

    float* out       = (float*)d_out;
    float* out_awe   = out;
    float* out_alpha = out + (size_t)B_ * ENC_;

    cudaFuncSetAttribute(gemm_e_kernel,
                         cudaFuncAttributeMaxDynamicSharedMemorySize, SMEM_BYTES);

    att2_kernel<<<128, 512>>>(dech, Wdec, bdec);
    prepackB<<<FN_TOT * KF_TOT * 64 / 256, 256>>>(Wenc);

    dim3 g2(4, 196);                           // nchunk fastest -> A L2 reuse
    gemm_e_kernel<<<g2, 256, SMEM_BYTES>>>(enc, benc, Wfull);

    dim3 g3(2, B_);
    awe_kernel<<<g3, 256>>>(enc, bfull, out_alpha, out_awe);
}

// round 15
// speedup vs baseline: 1.2636x; 1.0162x over previous
#include <cuda_runtime.h>
#include <cuda_fp16.h>
#include <stdint.h>
#include <math.h>

#define B_    128
#define N_    196
#define ENC_  2048
#define DEC_  512
#define ATT_  512
#define M_    (B_ * N_)          // 25088 rows
#define KF_TOT (ENC_ / 16)       // 128 k16 fragments
#define FNP_TOT (ATT_ / 16)      // 32 fn-pairs

// gemm tiling: block 128m x 256n x 64k, 512 thr (4M x 4N warps), 2-stage
// stage: A raw fp32 128x64 (32KB) + B fp16 paired frag (32KB) = 64KB
#define NKS        32            // k-steps of 64
#define STAGE_U32  16384         // 64KB per stage
#define SMEM_BYTES (2 * STAGE_U32 * 4)   // 131072

// ---- scratch (__device__ globals: sanctioned no-alloc workaround) ----
__device__ float    g_att2[B_ * ATT_];
__device__ float    g_epart[M_ * 2];
__device__ uint32_t g_Bf2[FNP_TOT * KF_TOT * 128];  // B fp16 pair-frag, permuted k

// ============================================================
// helpers
// ============================================================
__device__ __forceinline__ uint32_t pack_h2(__half lo, __half hi) {
    __half2 p; p.x = lo; p.y = hi;
    return *reinterpret_cast<uint32_t*>(&p);
}
__device__ __forceinline__ uint32_t cvt2h(float hi, float lo) {
    uint32_t r;
    asm("cvt.rn.f16x2.f32 %0, %1, %2;" : "=r"(r) : "f"(hi), "f"(lo));
    return r;
}
__device__ __forceinline__ void cp16(uint32_t saddr, const void* g) {
    asm volatile("cp.async.cg.shared.global [%0], [%1], 16;\n" :: "r"(saddr), "l"(g));
}
__device__ __forceinline__ void cp_commit() { asm volatile("cp.async.commit_group;\n"); }
template <int NN> __device__ __forceinline__ void cp_wait() {
    asm volatile("cp.async.wait_group %0;\n" :: "n"(NN));
}
__device__ __forceinline__ void mma16816(float c[4], const uint32_t a[4], const uint32_t b[2]) {
    asm volatile(
        "mma.sync.aligned.m16n8k16.row.col.f32.f16.f16.f32 "
        "{%0,%1,%2,%3}, {%4,%5,%6,%7}, {%8,%9}, {%0,%1,%2,%3};\n"
        : "+f"(c[0]), "+f"(c[1]), "+f"(c[2]), "+f"(c[3])
        : "r"(a[0]), "r"(a[1]), "r"(a[2]), "r"(a[3]),
          "r"(b[0]), "r"(b[1]));
}

// ============================================================
// Kernel 1: att2 = decoder_hidden @ W_dec + b_dec   (R14 form, ~5us)
// ============================================================
__global__ __launch_bounds__(512)
void att2_kernel(const float* __restrict__ dec,
                 const float* __restrict__ Wdec,
                 const float* __restrict__ bdec) {
    __shared__ float ds[16][DEC_];
    const int tid = threadIdx.x;
    const int ax  = blockIdx.x & 15;
    const int bgp = blockIdx.x >> 4;
    const int a  = ax * 32 + (tid & 31);
    const int bl = tid >> 5;
    const int b  = bgp * 16 + bl;

#pragma unroll
    for (int j = 0; j < 4; j++) {
        int lin = j * 512 + tid;
        int row = lin >> 7;
        int c4  = lin & 127;
        *reinterpret_cast<float4*>(&ds[row][c4 * 4]) =
            *reinterpret_cast<const float4*>(&dec[(size_t)(bgp * 16 + row) * DEC_ + c4 * 4]);
    }
    __syncthreads();

    float a0 = 0.f, a1 = 0.f, a2 = 0.f, a3 = 0.f;
#pragma unroll 4
    for (int d = 0; d < DEC_; d += 4) {
        float w0 = Wdec[(size_t)(d + 0) * ATT_ + a];
        float w1 = Wdec[(size_t)(d + 1) * ATT_ + a];
        float w2 = Wdec[(size_t)(d + 2) * ATT_ + a];
        float w3 = Wdec[(size_t)(d + 3) * ATT_ + a];
        a0 += ds[bl][d + 0] * w0;
        a1 += ds[bl][d + 1] * w1;
        a2 += ds[bl][d + 2] * w2;
        a3 += ds[bl][d + 3] * w3;
    }
    g_att2[(size_t)b * ATT_ + a] = ((a0 + a1) + (a2 + a3)) + bdec[a];
}

// ============================================================
// Prepack B: W_enc [K][N] -> fp16 PAIRED frag layout, permuted k
//   layout [fnp][kf][lane][rr4]; rr = fn_sub*2 + kreg
//   n = fnp*16 + fn_sub*8 + (lane>>2)
//   k = kf*16 + (lane&3)*4 + kreg*2   (A uses same permutation)
// ============================================================
__global__ void prepackB(const float* __restrict__ Wenc) {
    int idx = blockIdx.x * 256 + threadIdx.x;
    int rr   = idx & 3;
    int lane = (idx >> 2) & 31;
    int kf   = (idx >> 7) & (KF_TOT - 1);
    int fnp  = idx >> 14;
    int n = fnp * 16 + (rr >> 1) * 8 + (lane >> 2);
    int k = kf * 16 + (lane & 3) * 4 + (rr & 1) * 2;
    float v0 = Wenc[(size_t)k * ATT_ + n];
    float v1 = Wenc[(size_t)(k + 1) * ATT_ + n];
    g_Bf2[idx] = pack_h2(__float2half_rn(v0), __float2half_rn(v1));
}

// ============================================================
// Kernel 2: HMMA GEMM (1-term fp16, A converted in-kernel) + epilogue
//   block 128m x 256n x 64k; 16 warps (4M x 4N), warp tile 32x64
//   grid (nchunk=2 fastest, mtile=196); 2-stage cp.async, 1 CTA/SM
// ============================================================
__global__ __launch_bounds__(512, 1)
void gemm_e_kernel(const float* __restrict__ enc,
                   const float* __restrict__ benc,
                   const float* __restrict__ Wfull) {
    extern __shared__ uint32_t sm[];   // 2 stages x 16384 u32
    const int tid = threadIdx.x;
    const int lane = tid & 31, wid = tid >> 5;
    const int warpM = wid & 3, warpN = wid >> 2;   // 4M x 4N
    const int nchunk = blockIdx.x;     // 0..1
    const int mtile  = blockIdx.y;     // 0..195
    const int m0g = mtile * 128;
    const int g = lane >> 2, tig = lane & 3;

    const uint32_t smbase = (uint32_t)__cvta_generic_to_shared(sm);

    float acc[2][8][4];
#pragma unroll
    for (int i = 0; i < 2; i++)
#pragma unroll
        for (int j = 0; j < 8; j++)
#pragma unroll
            for (int q = 0; q < 4; q++) acc[i][j][q] = 0.f;

    // ---- async load of k-step ks (64 k): A raw fp32 + B fp16; 8/thread ----
    auto issue = [&](int ks, int st) {
        const uint32_t so = smbase + (uint32_t)(st * STAGE_U32) * 4u;
#pragma unroll
        for (int i = 0; i < 8; i++) {
            int c = i * 512 + tid;           // 0..4095
            uint32_t dst;
            const void* src;
            if (c < 2048) {                  // A: row(128) x chunk16(16B=4 fp32)
                int row = c >> 4, cc = c & 15;
                int csw = (cc + row * 4) & 15;
                src = enc + (size_t)(m0g + row) * ENC_ + ks * 64 + cc * 4;
                dst = so + (uint32_t)(row * 64 + csw * 4) * 4u;
            } else {                         // B paired: fnp16 kf4 ln32
                int d = c - 2048;
                int fnp = d >> 7, kf = (d >> 5) & 3, ln = d & 31;
                src = g_Bf2 + ((size_t)(nchunk * 16 + fnp) * KF_TOT + (ks * 4 + kf)) * 128 + ln * 4;
                dst = so + (uint32_t)(8192 + (fnp * 4 + kf) * 128 + ln * 4) * 4u;
            }
            cp16(dst, src);
        }
        cp_commit();
    };

    issue(0, 0);

    for (int s = 0; s < NKS; s++) {
        const int st = s & 1;
        cp_wait<0>();                 // only group s outstanding here
        __syncthreads();              // all warps done reading buffer s-1
        if (s + 1 < NKS) issue(s + 1, st ^ 1);

        const int sb = st * STAGE_U32;
#pragma unroll
        for (int kf = 0; kf < 4; kf++) {
            // A fragments: 2x LDS.128 fp32 + 4 cvt per fm
            uint32_t a[2][4];
#pragma unroll
            for (int fm = 0; fm < 2; fm++) {
                int rbase = (warpM * 2 + fm) * 16;
                int r0 = rbase + g, r1 = rbase + 8 + g;
                int c0 = ((kf * 4 + tig) + r0 * 4) & 15;
                int c1 = ((kf * 4 + tig) + r1 * 4) & 15;
                float4 f0 = *reinterpret_cast<const float4*>(&sm[sb + r0 * 64 + c0 * 4]);
                float4 f1 = *reinterpret_cast<const float4*>(&sm[sb + r1 * 64 + c1 * 4]);
                a[fm][0] = cvt2h(f0.y, f0.x);
                a[fm][1] = cvt2h(f1.y, f1.x);
                a[fm][2] = cvt2h(f0.w, f0.z);
                a[fm][3] = cvt2h(f1.w, f1.z);
            }
            // B fragments: 4x LDS.128 (paired fn)
            uint32_t b[8][2];
#pragma unroll
            for (int fnp = 0; fnp < 4; fnp++) {
                int fnpAbs = warpN * 4 + fnp;
                uint4 v = *reinterpret_cast<const uint4*>(
                    &sm[sb + 8192 + (fnpAbs * 4 + kf) * 128 + lane * 4]);
                b[fnp * 2][0] = v.x;      b[fnp * 2][1] = v.y;
                b[fnp * 2 + 1][0] = v.z;  b[fnp * 2 + 1][1] = v.w;
            }
#pragma unroll
            for (int fm = 0; fm < 2; fm++)
#pragma unroll
                for (int fn = 0; fn < 8; fn++)
                    mma16816(acc[fm][fn], a[fm], b[fn]);
        }
    }

    // ---- fused epilogue: v = relu(acc + b_enc + att2); e += v * W_full ----
    float ep[2][2] = {{0.f, 0.f}, {0.f, 0.f}};
#pragma unroll
    for (int fm = 0; fm < 2; fm++) {
        int r0 = warpM * 32 + fm * 16 + g;
        int b0 = (m0g + r0) / N_;
        int b1 = (m0g + r0 + 8) / N_;
#pragma unroll
        for (int fn = 0; fn < 8; fn++) {
            int a0i = nchunk * 256 + warpN * 64 + fn * 8 + tig * 2;
            int a1i = a0i + 1;
            float w0 = Wfull[a0i], w1 = Wfull[a1i];
            float be0 = benc[a0i], be1 = benc[a1i];
            float t00 = g_att2[b0 * ATT_ + a0i];
            float t01 = g_att2[b0 * ATT_ + a1i];
            float t10 = g_att2[b1 * ATT_ + a0i];
            float t11 = g_att2[b1 * ATT_ + a1i];
            ep[fm][0] += fmaxf(acc[fm][fn][0] + be0 + t00, 0.f) * w0;
            ep[fm][0] += fmaxf(acc[fm][fn][1] + be1 + t01, 0.f) * w1;
            ep[fm][1] += fmaxf(acc[fm][fn][2] + be0 + t10, 0.f) * w0;
            ep[fm][1] += fmaxf(acc[fm][fn][3] + be1 + t11, 0.f) * w1;
        }
    }
#pragma unroll
    for (int off = 1; off <= 2; off <<= 1)
#pragma unroll
        for (int fm = 0; fm < 2; fm++) {
            ep[fm][0] += __shfl_xor_sync(0xffffffffu, ep[fm][0], off);
            ep[fm][1] += __shfl_xor_sync(0xffffffffu, ep[fm][1], off);
        }

    __syncthreads();
    float* e_red = reinterpret_cast<float*>(sm);  // [128][4]
    if (tig == 0) {
#pragma unroll
        for (int fm = 0; fm < 2; fm++) {
            int r0 = warpM * 32 + fm * 16 + g;
            e_red[r0 * 4 + warpN]       = ep[fm][0];
            e_red[(r0 + 8) * 4 + warpN] = ep[fm][1];
        }
    }
    __syncthreads();
    if (tid < 128) {
        float e = (e_red[tid * 4] + e_red[tid * 4 + 1])
                + (e_red[tid * 4 + 2] + e_red[tid * 4 + 3]);
        g_epart[(size_t)(m0g + tid) * 2 + nchunk] = e;
    }
}

// ============================================================
// Kernel 3: fused softmax + awe (DRAM-transfer-bound)
// ============================================================
__global__ void awe_kernel(const float* __restrict__ enc,
                           const float* __restrict__ bfull_p,
                           float* __restrict__ out_alpha,
                           float* __restrict__ out_awe) {
    __shared__ float al[N_];
    __shared__ float red[256];
    int b = blockIdx.y, tid = threadIdx.x;
    float bfull = *bfull_p;

    // ---- softmax over n (196) ----
    float ev = -INFINITY;
    float sval = 0.f;
    if (tid < N_) {
        const float* p = &g_epart[(size_t)(b * N_ + tid) * 2];
        sval = bfull + p[0] + p[1];
        ev = sval;
    }
    red[tid] = ev; __syncthreads();
#pragma unroll
    for (int off = 128; off > 0; off >>= 1) {
        if (tid < off) red[tid] = fmaxf(red[tid], red[tid + off]);
        __syncthreads();
    }
    float mx = red[0]; __syncthreads();
    float ex = 0.f;
    if (tid < N_) ex = expf(sval - mx);
    red[tid] = ex; __syncthreads();
#pragma unroll
    for (int off = 128; off > 0; off >>= 1) {
        if (tid < off) red[tid] += red[tid + off];
        __syncthreads();
    }
    float inv = 1.f / red[0];
    if (tid < N_) {
        float a = ex * inv;
        al[tid] = a;
        if (blockIdx.x == 0) out_alpha[b * N_ + tid] = a;
    }
    __syncthreads();

    // ---- weighted encoding: float4, 7 accumulator chains (28*7=196) ----
    int e0 = (blockIdx.x * 256 + tid) * 4;
    const float4* p = reinterpret_cast<const float4*>(enc + (size_t)b * N_ * ENC_ + e0);
    float4 a0 = make_float4(0.f, 0.f, 0.f, 0.f);
    float4 a1 = make_float4(0.f, 0.f, 0.f, 0.f);
    float4 a2 = make_float4(0.f, 0.f, 0.f, 0.f);
    float4 a3 = make_float4(0.f, 0.f, 0.f, 0.f);
    float4 a4 = make_float4(0.f, 0.f, 0.f, 0.f);
    float4 a5 = make_float4(0.f, 0.f, 0.f, 0.f);
    float4 a6 = make_float4(0.f, 0.f, 0.f, 0.f);
#pragma unroll 4
    for (int n = 0; n < 28; n++) {
        float4 v0 = p[(size_t)n * (ENC_ / 4)];
        float4 v1 = p[(size_t)(n + 28) * (ENC_ / 4)];
        float4 v2 = p[(size_t)(n + 56) * (ENC_ / 4)];
        float4 v3 = p[(size_t)(n + 84) * (ENC_ / 4)];
        float4 v4 = p[(size_t)(n + 112) * (ENC_ / 4)];
        float4 v5 = p[(size_t)(n + 140) * (ENC_ / 4)];
        float4 v6 = p[(size_t)(n + 168) * (ENC_ / 4)];
        float w0 = al[n], w1 = al[n + 28], w2 = al[n + 56], w3 = al[n + 84];
        float w4 = al[n + 112], w5 = al[n + 140], w6 = al[n + 168];
        a0.x += w0 * v0.x; a0.y += w0 * v0.y; a0.z += w0 * v0.z; a0.w += w0 * v0.w;
        a1.x += w1 * v1.x; a1.y += w1 * v1.y; a1.z += w1 * v1.z; a1.w += w1 * v1.w;
        a2.x += w2 * v2.x; a2.y += w2 * v2.y; a2.z += w2 * v2.z; a2.w += w2 * v2.w;
        a3.x += w3 * v3.x; a3.y += w3 * v3.y; a3.z += w3 * v3.z; a3.w += w3 * v3.w;
        a4.x += w4 * v4.x; a4.y += w4 * v4.y; a4.z += w4 * v4.z; a4.w += w4 * v4.w;
        a5.x += w5 * v5.x; a5.y += w5 * v5.y; a5.z += w5 * v5.z; a5.w += w5 * v5.w;
        a6.x += w6 * v6.x; a6.y += w6 * v6.y; a6.z += w6 * v6.z; a6.w += w6 * v6.w;
    }
    float4 r;
    r.x = ((a0.x + a1.x) + (a2.x + a3.x)) + ((a4.x + a5.x) + a6.x);
    r.y = ((a0.y + a1.y) + (a2.y + a3.y)) + ((a4.y + a5.y) + a6.y);
    r.z = ((a0.z + a1.z) + (a2.z + a3.z)) + ((a4.z + a5.z) + a6.z);
    r.w = ((a0.w + a1.w) + (a2.w + a3.w)) + ((a4.w + a5.w) + a6.w);
    *reinterpret_cast<float4*>(out_awe + (size_t)b * ENC_ + e0) = r;
}

// ============================================================
extern "C" void kernel_launch(void* const* d_in, const int* in_sizes, int n_in,
                              void* d_out, int out_size) {
    const float* enc   = (const float*)d_in[0];
    const float* dech  = (const float*)d_in[1];
    const float* Wenc  = (const float*)d_in[2];
    const float* benc  = (const float*)d_in[3];
    const float* Wdec  = (const float*)d_in[4];
    const float* bdec  = (const float*)d_in[5];
    const float* Wfull = (const float*)d_in[6];
    const float* bfull = (const float*)d_in[7];

    float* out       = (float*)d_out;
    float* out_awe   = out;
    float* out_alpha = out + (size_t)B_ * ENC_;

    cudaFuncSetAttribute(gemm_e_kernel,
                         cudaFuncAttributeMaxDynamicSharedMemorySize, SMEM_BYTES);

    att2_kernel<<<128, 512>>>(dech, Wdec, bdec);
    prepackB<<<FNP_TOT * KF_TOT * 128 / 256, 256>>>(Wenc);

    dim3 g2(2, 196);                           // nchunk fastest -> A L2 reuse
    gemm_e_kernel<<<g2, 512, SMEM_BYTES>>>(enc, benc, Wfull);

    dim3 g3(2, B_);
    awe_kernel<<<g3, 256>>>(enc, bfull, out_alpha, out_awe);
}